// round 14
// baseline (speedup 1.0000x reference)
#include <cuda_runtime.h>
#include <cuda_fp16.h>

// DistMult edge score: out[e] = sum_d node[src[e]][d] * rel[e][d] * node[dst[e]][d]
// N_NODES=100000, N_EDGES=600000, DIM=128, int32 indices.
//
// R13 model (closed): scorer pinned at LTS floor (55.6us); total 61.6us =
// convert (~6us) + scorer, serialized. R14: overlap them with PDL.
// The scorer's index + rel-stream loads don't depend on the fp16 table, so
// they issue BEFORE cudaGridDependencySynchronize(); only the node gathers
// wait for convert completion. Expected: convert cost hidden, ~57us total.

#define DIM       128
#define DIM4      32
#define EPW       4
#define MAX_NODES 100000

__device__ __half g_node16[(size_t)MAX_NODES * DIM];   // 25.6 MB scratch

// ---- Kernel 1: fp32 node table -> fp16 scratch ----
__global__ __launch_bounds__(256)
void convert_kernel(const float* __restrict__ node_emb, int total4) {
    int i = blockIdx.x * blockDim.x + threadIdx.x;
    if (i >= total4) return;
    float4 v = reinterpret_cast<const float4*>(node_emb)[i];
    __half2 a = __floats2half2_rn(v.x, v.y);
    __half2 b = __floats2half2_rn(v.z, v.w);
    uint2 o;
    o.x = *reinterpret_cast<unsigned int*>(&a);
    o.y = *reinterpret_cast<unsigned int*>(&b);
    reinterpret_cast<uint2*>(g_node16)[i] = o;
    // implicit completion trigger at kernel end releases the PDL dependency
}

// ---- Kernel 2: scorer; pre-sync = index + rel loads, post-sync = gathers ----
__global__ __launch_bounds__(256)
void distmult_kernel(const float* __restrict__ rel_emb,
                     const int* __restrict__ src,
                     const int* __restrict__ dst,
                     float* __restrict__ out,
                     int n_edges,
                     int n_nodes) {
    int warp  = (blockIdx.x * blockDim.x + threadIdx.x) >> 5;
    int lane  = threadIdx.x & 31;
    int ebase = warp * EPW;

    const uint2*  __restrict__ node16 = reinterpret_cast<const uint2*>(g_node16);
    const float4* __restrict__ rel4   = reinterpret_cast<const float4*>(rel_emb);
    int nmax = min(n_nodes, MAX_NODES) - 1;

    int s[EPW], d[EPW];
    float4 rv[EPW];
    bool active = ebase < n_edges;

    if (active) {
        // -------- Pre-dependency phase: touches only harness inputs --------
        #pragma unroll
        for (int i = 0; i < EPW; i++) {
            int e = ebase + i;
            if (e >= n_edges) e = n_edges - 1;   // 600000 % 4 == 0 anyway
            s[i] = min(max(src[e], 0), nmax);
            d[i] = min(max(dst[e], 0), nmax);
            rv[i] = __ldcs(rel4 + (unsigned)e * DIM4 + lane);  // fp32 stream
        }
    }

    // Wait for convert_kernel's writes to g_node16 to be visible.
    cudaGridDependencySynchronize();

    if (!active) return;

    // -------- Post-dependency: gather fp16 node rows --------
    uint2 hq[EPW], tq[EPW];
    #pragma unroll
    for (int i = 0; i < EPW; i++) {
        hq[i] = node16[(unsigned)s[i] * DIM4 + lane];
        tq[i] = node16[(unsigned)d[i] * DIM4 + lane];
    }

    float acc[EPW];
    #pragma unroll
    for (int i = 0; i < EPW; i++) {
        __half2 h01 = *reinterpret_cast<__half2*>(&hq[i].x);
        __half2 h23 = *reinterpret_cast<__half2*>(&hq[i].y);
        __half2 t01 = *reinterpret_cast<__half2*>(&tq[i].x);
        __half2 t23 = *reinterpret_cast<__half2*>(&tq[i].y);
        float2 hA = __half22float2(h01), hB = __half22float2(h23);
        float2 tA = __half22float2(t01), tB = __half22float2(t23);
        acc[i] = hA.x * rv[i].x * tA.x
               + hA.y * rv[i].y * tA.y
               + hB.x * rv[i].z * tB.x
               + hB.y * rv[i].w * tB.y;
    }

    #pragma unroll
    for (int off = 16; off > 0; off >>= 1) {
        #pragma unroll
        for (int i = 0; i < EPW; i++)
            acc[i] += __shfl_xor_sync(0xffffffffu, acc[i], off);
    }

    if (lane < EPW) {
        int e = ebase + lane;
        if (e < n_edges) {
            float v = (lane == 0) ? acc[0] : (lane == 1) ? acc[1]
                    : (lane == 2) ? acc[2] : acc[3];
            out[e] = v;
        }
    }
}

extern "C" void kernel_launch(void* const* d_in, const int* in_sizes, int n_in,
                              void* d_out, int out_size) {
    const float* node_emb = (const float*)d_in[0];
    const float* rel_emb  = (const float*)d_in[1];
    const int*   src      = (const int*)d_in[2];
    const int*   dst      = (const int*)d_in[3];
    float* out = (float*)d_out;

    int n_edges = in_sizes[1] / DIM;
    int n_nodes = in_sizes[0] / DIM;
    int n_conv  = min(n_nodes, MAX_NODES);

    int total4 = n_conv * DIM4;
    convert_kernel<<<(total4 + 255) / 256, 256>>>(node_emb, total4);

    int threads = 256;
    int edges_per_block = (threads / 32) * EPW;       // 32
    int blocks = (n_edges + edges_per_block - 1) / edges_per_block;

    // Scorer with programmatic dependent launch: its blocks may start while
    // convert_kernel drains; pre-sync code overlaps the conversion.
    cudaLaunchConfig_t cfg = {};
    cfg.gridDim  = dim3((unsigned)blocks, 1, 1);
    cfg.blockDim = dim3((unsigned)threads, 1, 1);
    cfg.dynamicSmemBytes = 0;
    cfg.stream = 0;   // legacy default stream (same as <<<>>> launches above)
    cudaLaunchAttribute attr[1];
    attr[0].id = cudaLaunchAttributeProgrammaticStreamSerialization;
    attr[0].val.programmaticStreamSerializationAllowed = 1;
    cfg.attrs = attr;
    cfg.numAttrs = 1;

    cudaError_t err = cudaLaunchKernelEx(&cfg, distmult_kernel,
                                         rel_emb, src, dst, out,
                                         n_edges, n_nodes);
    if (err != cudaSuccess) {
        // Fallback: plain serialized launch (R13 behavior).
        distmult_kernel<<<blocks, threads>>>(rel_emb, src, dst, out,
                                             n_edges, n_nodes);
    }
}

// round 15
// speedup vs baseline: 1.1601x; 1.1601x over previous
#include <cuda_runtime.h>
#include <cuda_fp16.h>

// DistMult edge score: out[e] = sum_d node[src[e]][d] * rel[e][d] * node[dst[e]][d]
// N_NODES=100000, N_EDGES=600000, DIM=128, int32 indices.
//
// FINAL (= R13, measured best: 61.6us, rel_err 2.94e-4).
//
// Closed model, every axis measured:
//   - Scorer is pinned at the LTS (L2-bandwidth) chip cap: ~620MB of L2 bytes
//     (307MB fp32 rel stream + 307MB fp16 node gathers) at ~11.3TB/s
//     -> 55.5us, reproduced across 4 rounds regardless of occupancy/MLP.
//   - fp16 node scratch is the only structural win (930->620MB L2 bytes;
//     rel_err 2.9e-4 vs 1e-3 threshold; bf16 would breach at ~1.2e-3).
//   - Falsified: EPW=8 register batching (ptxas 40-reg wall), cp.async
//     staging + pipelines (barrier cadence), int4 index loads (reg growth),
//     L2 createpolicy hints (cost, no benefit), wider convert threads,
//     PDL convert/scorer overlap (sync cost + co-residency contention).
//
// Scorer: warp per 4 edges; lane l owns dims [4l,4l+4). Node rows read as
// uint2 (4 halves, 256B/warp); rel rows as float4 via __ldcs (512B/warp,
// evict-first keeps the fp16 table + gather working set L2-resident).

#define DIM       128
#define DIM4      32            // 16B groups per fp32 row / uint2 groups per fp16 row
#define EPW       4             // edges per warp
#define MAX_NODES 100000

__device__ __half g_node16[(size_t)MAX_NODES * DIM];   // 25.6 MB scratch

// ---- Kernel 1: fp32 node table -> fp16 scratch (16B read / 8B write per thread) ----
__global__ __launch_bounds__(256)
void convert_kernel(const float* __restrict__ node_emb, int total4) {
    int i = blockIdx.x * blockDim.x + threadIdx.x;
    if (i >= total4) return;
    float4 v = reinterpret_cast<const float4*>(node_emb)[i];
    __half2 a = __floats2half2_rn(v.x, v.y);
    __half2 b = __floats2half2_rn(v.z, v.w);
    uint2 o;
    o.x = *reinterpret_cast<unsigned int*>(&a);
    o.y = *reinterpret_cast<unsigned int*>(&b);
    reinterpret_cast<uint2*>(g_node16)[i] = o;
}

// ---- Kernel 2: scorer (at the LTS floor for this algorithm) ----
__global__ __launch_bounds__(256)
void distmult_kernel(const float* __restrict__ rel_emb,
                     const int* __restrict__ src,
                     const int* __restrict__ dst,
                     float* __restrict__ out,
                     int n_edges,
                     int n_nodes) {
    int warp  = (blockIdx.x * blockDim.x + threadIdx.x) >> 5;
    int lane  = threadIdx.x & 31;
    int ebase = warp * EPW;
    if (ebase >= n_edges) return;

    const uint2*  __restrict__ node16 = reinterpret_cast<const uint2*>(g_node16);
    const float4* __restrict__ rel4   = reinterpret_cast<const float4*>(rel_emb);
    int nmax = min(n_nodes, MAX_NODES) - 1;

    // Index loads (warp-uniform broadcast).
    int s[EPW], d[EPW];
    #pragma unroll
    for (int i = 0; i < EPW; i++) {
        int e = ebase + i;
        if (e >= n_edges) e = n_edges - 1;     // 600000 % 4 == 0 anyway
        s[i] = min(max(src[e], 0), nmax);
        d[i] = min(max(dst[e], 0), nmax);
    }

    // Front-batched loads. Lane l owns dims [4l, 4l+4):
    //   node rows: uint2 = 4 halves (8B) -> 256B/warp
    //   rel row:   float4 (16B, streaming __ldcs) -> 512B/warp
    uint2  hq[EPW], tq[EPW];
    float4 rv[EPW];
    #pragma unroll
    for (int i = 0; i < EPW; i++) {
        hq[i] = node16[(unsigned)s[i] * DIM4 + lane];
        tq[i] = node16[(unsigned)d[i] * DIM4 + lane];
        rv[i] = __ldcs(rel4 + (unsigned)(ebase + i) * DIM4 + lane);
    }

    float acc[EPW];
    #pragma unroll
    for (int i = 0; i < EPW; i++) {
        __half2 h01 = *reinterpret_cast<__half2*>(&hq[i].x);
        __half2 h23 = *reinterpret_cast<__half2*>(&hq[i].y);
        __half2 t01 = *reinterpret_cast<__half2*>(&tq[i].x);
        __half2 t23 = *reinterpret_cast<__half2*>(&tq[i].y);
        float2 hA = __half22float2(h01), hB = __half22float2(h23);
        float2 tA = __half22float2(t01), tB = __half22float2(t23);
        acc[i] = hA.x * rv[i].x * tA.x
               + hA.y * rv[i].y * tA.y
               + hB.x * rv[i].z * tB.x
               + hB.y * rv[i].w * tB.y;
    }

    #pragma unroll
    for (int off = 16; off > 0; off >>= 1) {
        #pragma unroll
        for (int i = 0; i < EPW; i++)
            acc[i] += __shfl_xor_sync(0xffffffffu, acc[i], off);
    }

    if (lane < EPW) {
        int e = ebase + lane;
        if (e < n_edges) {
            float v = (lane == 0) ? acc[0] : (lane == 1) ? acc[1]
                    : (lane == 2) ? acc[2] : acc[3];
            out[e] = v;
        }
    }
}

extern "C" void kernel_launch(void* const* d_in, const int* in_sizes, int n_in,
                              void* d_out, int out_size) {
    const float* node_emb = (const float*)d_in[0];
    const float* rel_emb  = (const float*)d_in[1];
    const int*   src      = (const int*)d_in[2];
    const int*   dst      = (const int*)d_in[3];
    float* out = (float*)d_out;

    int n_edges = in_sizes[1] / DIM;
    int n_nodes = in_sizes[0] / DIM;
    int n_conv  = min(n_nodes, MAX_NODES);

    int total4 = n_conv * DIM4;                       // 16B groups to convert
    convert_kernel<<<(total4 + 255) / 256, 256>>>(node_emb, total4);

    int threads = 256;
    int edges_per_block = (threads / 32) * EPW;       // 32
    int blocks = (n_edges + edges_per_block - 1) / edges_per_block;
    distmult_kernel<<<blocks, threads>>>(rel_emb, src, dst, out,
                                         n_edges, n_nodes);
}

// round 16
// speedup vs baseline: 1.1643x; 1.0036x over previous
#include <cuda_runtime.h>
#include <cuda_fp16.h>

// DistMult edge score: out[e] = sum_d node[src[e]][d] * rel[e][d] * node[dst[e]][d]
// N_NODES=100000, N_EDGES=600000, DIM=128, int32 indices.
//
// TERMINAL KERNEL (measured best 61.6us; R15 re-run 62.2us = variance band).
//
// Closed model, every axis measured over R3-R15:
//   - Scorer pinned at the LTS (L2-bandwidth) chip cap: ~620MB L2 bytes
//     (307MB fp32 rel stream + 307MB fp16 node gathers) at ~11.3TB/s
//     -> 55.0-55.6us across 5 profiles, invariant to occupancy/MLP tuning.
//   - fp16 node scratch is the one structural win (930->620MB L2 bytes;
//     rel_err 2.9e-4 vs 1e-3 threshold). int8 would give ~9e-3: breach.
//     fp16 rel would ADD net L2 bytes (615 vs 307MB): rejected.
//   - Falsified: EPW=8 register batching (ptxas ~40-reg wall), cp.async
//     staging & 3-stage pipelines (barrier cadence), int4 index loads,
//     L2 createpolicy hints, wider convert threads, PDL overlap (grid-wide
//     sync cost + co-residency contention), cross-call caching (forbidden).
//
// Scorer: warp per 4 edges; lane l owns dims [4l,4l+4). Node rows read as
// uint2 (4 halves, 256B/warp); rel rows as float4 via __ldcs (512B/warp,
// evict-first keeps the fp16 table + gather working set L2-resident).

#define DIM       128
#define DIM4      32            // 16B groups per fp32 row / uint2 groups per fp16 row
#define EPW       4             // edges per warp
#define MAX_NODES 100000

__device__ __half g_node16[(size_t)MAX_NODES * DIM];   // 25.6 MB scratch

// ---- Kernel 1: fp32 node table -> fp16 scratch (16B read / 8B write per thread) ----
__global__ __launch_bounds__(256)
void convert_kernel(const float* __restrict__ node_emb, int total4) {
    int i = blockIdx.x * blockDim.x + threadIdx.x;
    if (i >= total4) return;
    float4 v = reinterpret_cast<const float4*>(node_emb)[i];
    __half2 a = __floats2half2_rn(v.x, v.y);
    __half2 b = __floats2half2_rn(v.z, v.w);
    uint2 o;
    o.x = *reinterpret_cast<unsigned int*>(&a);
    o.y = *reinterpret_cast<unsigned int*>(&b);
    reinterpret_cast<uint2*>(g_node16)[i] = o;
}

// ---- Kernel 2: scorer (at the LTS floor for this algorithm) ----
__global__ __launch_bounds__(256)
void distmult_kernel(const float* __restrict__ rel_emb,
                     const int* __restrict__ src,
                     const int* __restrict__ dst,
                     float* __restrict__ out,
                     int n_edges,
                     int n_nodes) {
    int warp  = (blockIdx.x * blockDim.x + threadIdx.x) >> 5;
    int lane  = threadIdx.x & 31;
    int ebase = warp * EPW;
    if (ebase >= n_edges) return;

    const uint2*  __restrict__ node16 = reinterpret_cast<const uint2*>(g_node16);
    const float4* __restrict__ rel4   = reinterpret_cast<const float4*>(rel_emb);
    int nmax = min(n_nodes, MAX_NODES) - 1;

    // Index loads (warp-uniform broadcast).
    int s[EPW], d[EPW];
    #pragma unroll
    for (int i = 0; i < EPW; i++) {
        int e = ebase + i;
        if (e >= n_edges) e = n_edges - 1;     // 600000 % 4 == 0 anyway
        s[i] = min(max(src[e], 0), nmax);
        d[i] = min(max(dst[e], 0), nmax);
    }

    // Front-batched loads. Lane l owns dims [4l, 4l+4):
    //   node rows: uint2 = 4 halves (8B) -> 256B/warp
    //   rel row:   float4 (16B, streaming __ldcs) -> 512B/warp
    uint2  hq[EPW], tq[EPW];
    float4 rv[EPW];
    #pragma unroll
    for (int i = 0; i < EPW; i++) {
        hq[i] = node16[(unsigned)s[i] * DIM4 + lane];
        tq[i] = node16[(unsigned)d[i] * DIM4 + lane];
        rv[i] = __ldcs(rel4 + (unsigned)(ebase + i) * DIM4 + lane);
    }

    float acc[EPW];
    #pragma unroll
    for (int i = 0; i < EPW; i++) {
        __half2 h01 = *reinterpret_cast<__half2*>(&hq[i].x);
        __half2 h23 = *reinterpret_cast<__half2*>(&hq[i].y);
        __half2 t01 = *reinterpret_cast<__half2*>(&tq[i].x);
        __half2 t23 = *reinterpret_cast<__half2*>(&tq[i].y);
        float2 hA = __half22float2(h01), hB = __half22float2(h23);
        float2 tA = __half22float2(t01), tB = __half22float2(t23);
        acc[i] = hA.x * rv[i].x * tA.x
               + hA.y * rv[i].y * tA.y
               + hB.x * rv[i].z * tB.x
               + hB.y * rv[i].w * tB.y;
    }

    #pragma unroll
    for (int off = 16; off > 0; off >>= 1) {
        #pragma unroll
        for (int i = 0; i < EPW; i++)
            acc[i] += __shfl_xor_sync(0xffffffffu, acc[i], off);
    }

    if (lane < EPW) {
        int e = ebase + lane;
        if (e < n_edges) {
            float v = (lane == 0) ? acc[0] : (lane == 1) ? acc[1]
                    : (lane == 2) ? acc[2] : acc[3];
            out[e] = v;
        }
    }
}

extern "C" void kernel_launch(void* const* d_in, const int* in_sizes, int n_in,
                              void* d_out, int out_size) {
    const float* node_emb = (const float*)d_in[0];
    const float* rel_emb  = (const float*)d_in[1];
    const int*   src      = (const int*)d_in[2];
    const int*   dst      = (const int*)d_in[3];
    float* out = (float*)d_out;

    int n_edges = in_sizes[1] / DIM;
    int n_nodes = in_sizes[0] / DIM;
    int n_conv  = min(n_nodes, MAX_NODES);

    int total4 = n_conv * DIM4;                       // 16B groups to convert
    convert_kernel<<<(total4 + 255) / 256, 256>>>(node_emb, total4);

    int threads = 256;
    int edges_per_block = (threads / 32) * EPW;       // 32
    int blocks = (n_edges + edges_per_block - 1) / edges_per_block;
    distmult_kernel<<<blocks, threads>>>(rel_emb, src, dst, out,
                                         n_edges, n_nodes);
}